// round 5
// baseline (speedup 1.0000x reference)
#include <cuda_runtime.h>
#include <cstdint>

#define M_TOTAL 16384
#define N_TOTAL 1024
#define K_TOTAL 1024
#define L_CONV  20

// Scratch: reduced + tf32-rounded weight (device globals are the sanctioned scratch)
__device__ float g_W[(size_t)N_TOTAL * K_TOTAL];   // 4MB

// ---------------------------------------------------------------------------
// Baseline-PTX helpers (sm_80-era features only — no tcgen05 on this target)
// ---------------------------------------------------------------------------
__device__ __forceinline__ uint32_t smem_u32(const void* p) {
    uint32_t a;
    asm("{ .reg .u64 t; cvta.to.shared.u64 t, %1; cvt.u32.u64 %0, t; }"
        : "=r"(a) : "l"(p));
    return a;
}

__device__ __forceinline__ uint32_t f2tf32(float x) {
    uint32_t r;
    asm("cvt.rna.tf32.f32 %0, %1;" : "=r"(r) : "f"(x));
    return r;
}

__device__ __forceinline__ float tf32_rna_f(float x) {
    float r;
    asm("cvt.rna.tf32.f32 %0, %1;" : "=f"(r) : "f"(x));
    return r;
}

#define CP_ASYNC16(dst, src) \
    asm volatile("cp.async.cg.shared.global [%0], [%1], 16;" \
                 :: "r"(dst), "l"(src))
#define CP_COMMIT() asm volatile("cp.async.commit_group;")
#define CP_WAIT(n)  asm volatile("cp.async.wait_group %0;" :: "n"(n))

#define LDSM4(R, addr) \
    asm volatile("ldmatrix.sync.aligned.m8n8.x4.shared.b16 {%0,%1,%2,%3}, [%4];" \
                 : "=r"((R)[0]), "=r"((R)[1]), "=r"((R)[2]), "=r"((R)[3]) \
                 : "r"(addr))

#define MMA_TF32(D, A, B0, B1) \
    asm volatile("mma.sync.aligned.m16n8k8.row.col.f32.tf32.tf32.f32 " \
                 "{%0,%1,%2,%3}, {%4,%5,%6,%7}, {%8,%9}, {%0,%1,%2,%3};" \
                 : "+f"((D)[0]), "+f"((D)[1]), "+f"((D)[2]), "+f"((D)[3]) \
                 : "r"((A)[0]), "r"((A)[1]), "r"((A)[2]), "r"((A)[3]), \
                   "r"(B0), "r"(B1))

// ---------------------------------------------------------------------------
// Kernel 1: W[o,i] = round_tf32( (1/L) * sum_l conv_w[l,o,i] )
// ---------------------------------------------------------------------------
__global__ void reduce_w_kernel(const float* __restrict__ cw) {
    size_t i = (size_t)blockIdx.x * blockDim.x + threadIdx.x;  // over 262144 float4
    const float4* c4 = (const float4*)cw;
    const size_t plane = (size_t)N_TOTAL * K_TOTAL / 4;
    float4 a = c4[i];
    #pragma unroll
    for (int l = 1; l < L_CONV; ++l) {
        float4 v = c4[(size_t)l * plane + i];
        a.x += v.x; a.y += v.y; a.z += v.z; a.w += v.w;
    }
    const float s = 1.0f / (float)L_CONV;
    a.x = tf32_rna_f(a.x * s); a.y = tf32_rna_f(a.y * s);
    a.z = tf32_rna_f(a.z * s); a.w = tf32_rna_f(a.w * s);
    ((float4*)g_W)[i] = a;
}

// ---------------------------------------------------------------------------
// Kernel 2: tf32 GEMM via mma.sync — CTA tile 128x256, warp tile 64x64,
//           BK=32, 4-stage cp.async pipeline, 1 CTA/SM
//   A = x [16384 x 1024] row-major (K-major)
//   B = g_W [1024 x 1024] row-major in (n,k) == col-major B for .row.col mma
// ---------------------------------------------------------------------------
#define BM 128
#define BN 256
#define BK 32
#define ROWSTRIDE_B 144                      // 36 floats: padded, conflict-free
#define A_TILE_BYTES (BM * ROWSTRIDE_B)      // 18432
#define B_TILE_BYTES (BN * ROWSTRIDE_B)      // 36864
#define STAGE_BYTES (A_TILE_BYTES + B_TILE_BYTES)   // 55296
#define NSTAGES 4
#define GEMM_SMEM (NSTAGES * STAGE_BYTES)    // 221184
#define KTILES (K_TOTAL / BK)                // 32

__global__ __launch_bounds__(256, 1) void gemm_kernel(const float* __restrict__ x,
                                                      float* __restrict__ out) {
    extern __shared__ __align__(128) char smem[];
    const uint32_t sbase = smem_u32(smem);
    const int tid  = threadIdx.x;
    const int lane = tid & 31;
    const int warp = tid >> 5;
    const int wm = warp & 1;          // 2 warps along M (64 rows each)
    const int wn = warp >> 1;         // 4 warps along N (64 cols each)
    const int m0 = blockIdx.y * BM;
    const int n0 = blockIdx.x * BN;

    // --- global->smem copy: A 1024 16B-chunks (4/thread), B 2048 (8/thread)
    // chunk id = tid + j*256 -> row = (tid>>3) + 32*j, u = tid&7 (constant)
    const int crow = tid >> 3;
    const int cu   = tid & 7;
    const float* asrc0 = x   + (size_t)(m0 + crow) * K_TOTAL + cu * 4;
    const float* bsrc0 = g_W + (size_t)(n0 + crow) * K_TOTAL + cu * 4;
    const uint32_t adst0 = sbase + crow * ROWSTRIDE_B + cu * 16;
    const uint32_t bdst0 = sbase + A_TILE_BYTES + crow * ROWSTRIDE_B + cu * 16;

    // --- ldmatrix per-thread addresses (stage/k offsets added later)
    const int r8 = lane & 7;
    const int g  = lane >> 3;
    uint32_t a_addr[4], b_addr[4];
    #pragma unroll
    for (int mt = 0; mt < 4; ++mt) {
        int arow = wm * 64 + mt * 16 + ((g & 1) << 3) + r8;
        a_addr[mt] = sbase + arow * ROWSTRIDE_B + ((g >> 1) << 4);
    }
    #pragma unroll
    for (int p = 0; p < 4; ++p) {
        int brow = wn * 64 + p * 16 + ((g >> 1) << 3) + r8;
        b_addr[p] = sbase + A_TILE_BYTES + brow * ROWSTRIDE_B + ((g & 1) << 4);
    }

    float c[4][8][4];
    #pragma unroll
    for (int mt = 0; mt < 4; ++mt)
        #pragma unroll
        for (int nt = 0; nt < 8; ++nt)
            #pragma unroll
            for (int i = 0; i < 4; ++i) c[mt][nt][i] = 0.0f;

    // --- prologue: prefetch first NSTAGES-1 k-tiles
    #pragma unroll
    for (int s = 0; s < NSTAGES - 1; ++s) {
        uint32_t soff = s * STAGE_BYTES;
        #pragma unroll
        for (int j = 0; j < 4; ++j)
            CP_ASYNC16(adst0 + soff + j * (32 * ROWSTRIDE_B),
                       asrc0 + s * BK + (size_t)j * 32 * K_TOTAL);
        #pragma unroll
        for (int j = 0; j < 8; ++j)
            CP_ASYNC16(bdst0 + soff + j * (32 * ROWSTRIDE_B),
                       bsrc0 + s * BK + (size_t)j * 32 * K_TOTAL);
        CP_COMMIT();
    }

    // --- main loop
    for (int kt = 0; kt < KTILES; ++kt) {
        CP_WAIT(NSTAGES - 2);
        __syncthreads();

        int nload = kt + NSTAGES - 1;
        if (nload < KTILES) {
            uint32_t soff = (nload % NSTAGES) * STAGE_BYTES;
            #pragma unroll
            for (int j = 0; j < 4; ++j)
                CP_ASYNC16(adst0 + soff + j * (32 * ROWSTRIDE_B),
                           asrc0 + nload * BK + (size_t)j * 32 * K_TOTAL);
            #pragma unroll
            for (int j = 0; j < 8; ++j)
                CP_ASYNC16(bdst0 + soff + j * (32 * ROWSTRIDE_B),
                           bsrc0 + nload * BK + (size_t)j * 32 * K_TOTAL);
        }
        CP_COMMIT();

        const uint32_t soff = (kt % NSTAGES) * STAGE_BYTES;
        #pragma unroll
        for (int kk = 0; kk < 4; ++kk) {          // 4 x k8 steps
            uint32_t a[4][4], b[4][4];
            #pragma unroll
            for (int mt = 0; mt < 4; ++mt)
                LDSM4(a[mt], a_addr[mt] + soff + kk * 32);
            #pragma unroll
            for (int p = 0; p < 4; ++p)
                LDSM4(b[p], b_addr[p] + soff + kk * 32);
            // round A to tf32 (rna) — B was pre-rounded in reduce_w
            #pragma unroll
            for (int mt = 0; mt < 4; ++mt)
                #pragma unroll
                for (int i = 0; i < 4; ++i)
                    a[mt][i] = f2tf32(__uint_as_float(a[mt][i]));
            #pragma unroll
            for (int mt = 0; mt < 4; ++mt)
                #pragma unroll
                for (int nt = 0; nt < 8; ++nt) {
                    const int p = nt >> 1, h = (nt & 1) * 2;
                    MMA_TF32(c[mt][nt], a[mt], b[p][h], b[p][h + 1]);
                }
        }
    }

    // --- epilogue: direct float2 stores of raw y
    #pragma unroll
    for (int mt = 0; mt < 4; ++mt) {
        #pragma unroll
        for (int nt = 0; nt < 8; ++nt) {
            int row = m0 + wm * 64 + mt * 16 + (lane >> 2);
            int col = n0 + wn * 64 + nt * 8 + ((lane & 3) * 2);
            *(float2*)(out + (size_t)row * N_TOTAL + col) =
                make_float2(c[mt][nt][0], c[mt][nt][1]);
            *(float2*)(out + (size_t)(row + 8) * N_TOTAL + col) =
                make_float2(c[mt][nt][2], c[mt][nt][3]);
        }
    }
}

// ---------------------------------------------------------------------------
// Kernel 3: in-place RMSNorm over H=1024 per row
// ---------------------------------------------------------------------------
__global__ void rmsnorm_kernel(float* __restrict__ out, const float* __restrict__ nw) {
    const int row = blockIdx.x;
    const int tid = threadIdx.x;   // 256 threads, 1 float4 each
    float4* p = (float4*)(out + (size_t)row * 1024);
    float4 v = p[tid];
    float ss = v.x * v.x + v.y * v.y + v.z * v.z + v.w * v.w;
    #pragma unroll
    for (int o = 16; o > 0; o >>= 1) ss += __shfl_xor_sync(0xffffffffu, ss, o);
    __shared__ float sred[8];
    if ((tid & 31) == 0) sred[tid >> 5] = ss;
    __syncthreads();
    float tot = sred[0] + sred[1] + sred[2] + sred[3] +
                sred[4] + sred[5] + sred[6] + sred[7];
    float sc = rsqrtf(tot * (1.0f / 1024.0f) + 1e-6f);
    float4 w = ((const float4*)nw)[tid];
    v.x *= sc * w.x; v.y *= sc * w.y; v.z *= sc * w.z; v.w *= sc * w.w;
    p[tid] = v;
}

// ---------------------------------------------------------------------------
extern "C" void kernel_launch(void* const* d_in, const int* in_sizes, int n_in,
                              void* d_out, int out_size) {
    const float* xin = (const float*)d_in[0];
    const float* cw  = (const float*)d_in[1];
    const float* nw  = (const float*)d_in[2];
    float* out = (float*)d_out;

    reduce_w_kernel<<<512, 512>>>(cw);              // 262144 float4

    cudaFuncSetAttribute(gemm_kernel, cudaFuncAttributeMaxDynamicSharedMemorySize,
                         GEMM_SMEM);
    gemm_kernel<<<dim3(N_TOTAL / BN, M_TOTAL / BM), 256, GEMM_SMEM>>>(xin, out);

    rmsnorm_kernel<<<M_TOTAL, 256>>>(out, nw);
}

// round 6
// speedup vs baseline: 1.1187x; 1.1187x over previous
#include <cuda_runtime.h>
#include <cstdint>

#define M_TOTAL 16384
#define N_TOTAL 1024
#define K_TOTAL 1024
#define L_CONV  20

// Scratch: reduced + tf32-rounded weight (device globals are the sanctioned scratch)
__device__ float g_W[(size_t)N_TOTAL * K_TOTAL];   // 4MB

// ---------------------------------------------------------------------------
// Baseline-PTX helpers (sm_80-era features only — no tcgen05 on this target)
// ---------------------------------------------------------------------------
__device__ __forceinline__ uint32_t smem_u32(const void* p) {
    uint32_t a;
    asm("{ .reg .u64 t; cvta.to.shared.u64 t, %1; cvt.u32.u64 %0, t; }"
        : "=r"(a) : "l"(p));
    return a;
}

__device__ __forceinline__ uint32_t f2tf32(float x) {
    uint32_t r;
    asm("cvt.rna.tf32.f32 %0, %1;" : "=r"(r) : "f"(x));
    return r;
}

__device__ __forceinline__ float tf32_rna_f(float x) {
    float r;
    asm("cvt.rna.tf32.f32 %0, %1;" : "=f"(r) : "f"(x));
    return r;
}

#define CP_ASYNC16(dst, src) \
    asm volatile("cp.async.cg.shared.global [%0], [%1], 16;" \
                 :: "r"(dst), "l"(src))
#define CP_COMMIT() asm volatile("cp.async.commit_group;")
#define CP_WAIT(n)  asm volatile("cp.async.wait_group %0;" :: "n"(n))

#define LDSM4(R, addr) \
    asm volatile("ldmatrix.sync.aligned.m8n8.x4.shared.b16 {%0,%1,%2,%3}, [%4];" \
                 : "=r"((R)[0]), "=r"((R)[1]), "=r"((R)[2]), "=r"((R)[3]) \
                 : "r"(addr))

#define MMA_TF32(D, A, B0, B1) \
    asm volatile("mma.sync.aligned.m16n8k8.row.col.f32.tf32.tf32.f32 " \
                 "{%0,%1,%2,%3}, {%4,%5,%6,%7}, {%8,%9}, {%0,%1,%2,%3};" \
                 : "+f"((D)[0]), "+f"((D)[1]), "+f"((D)[2]), "+f"((D)[3]) \
                 : "r"((A)[0]), "r"((A)[1]), "r"((A)[2]), "r"((A)[3]), \
                   "r"(B0), "r"(B1))

// ---------------------------------------------------------------------------
// Kernel 1: W[o,i] = round_tf32( (1/L) * sum_l conv_w[l,o,i] )
// ---------------------------------------------------------------------------
__global__ void reduce_w_kernel(const float* __restrict__ cw) {
    size_t i = (size_t)blockIdx.x * blockDim.x + threadIdx.x;  // over 262144 float4
    const float4* c4 = (const float4*)cw;
    const size_t plane = (size_t)N_TOTAL * K_TOTAL / 4;
    float4 a = c4[i];
    #pragma unroll
    for (int l = 1; l < L_CONV; ++l) {
        float4 v = c4[(size_t)l * plane + i];
        a.x += v.x; a.y += v.y; a.z += v.z; a.w += v.w;
    }
    const float s = 1.0f / (float)L_CONV;
    a.x = tf32_rna_f(a.x * s); a.y = tf32_rna_f(a.y * s);
    a.z = tf32_rna_f(a.z * s); a.w = tf32_rna_f(a.w * s);
    ((float4*)g_W)[i] = a;
}

// ---------------------------------------------------------------------------
// Kernel 2: tf32 GEMM via mma.sync — CTA tile 128x128, 4 warps (warp tile
//           64x64), BK=32, 3-stage cp.async, 2 CTAs/SM for bubble hiding
//   A = x [16384 x 1024] row-major (K-major)
//   B = g_W [1024 x 1024] row-major in (n,k) == col-major B for .row.col mma
// ---------------------------------------------------------------------------
#define BM 128
#define BN 128
#define BK 32
#define ROWSTRIDE_B 144                      // 36 floats: padded, conflict-free
#define A_TILE_BYTES (BM * ROWSTRIDE_B)      // 18432
#define B_TILE_BYTES (BN * ROWSTRIDE_B)      // 18432
#define STAGE_BYTES (A_TILE_BYTES + B_TILE_BYTES)   // 36864
#define NSTAGES 3
#define GEMM_SMEM (NSTAGES * STAGE_BYTES)    // 110592 (x2 CTAs = 221184 <= 228KB)
#define KTILES (K_TOTAL / BK)                // 32

__global__ __launch_bounds__(128, 2) void gemm_kernel(const float* __restrict__ x,
                                                      float* __restrict__ out) {
    extern __shared__ __align__(128) char smem[];
    const uint32_t sbase = smem_u32(smem);
    const int tid  = threadIdx.x;
    const int lane = tid & 31;
    const int warp = tid >> 5;        // 0..3
    const int wm = warp & 1;          // 2 warps along M (64 rows each)
    const int wn = warp >> 1;         // 2 warps along N (64 cols each)
    const int m0 = blockIdx.y * BM;
    const int n0 = blockIdx.x * BN;

    // --- global->smem copy: A 1024 16B-chunks (8/thread), B 1024 (8/thread)
    // chunk id = tid + j*128 -> row = (tid>>3) + 16*j, u = tid&7 (constant)
    const int crow = tid >> 3;        // 0..15
    const int cu   = tid & 7;
    const float* asrc0 = x   + (size_t)(m0 + crow) * K_TOTAL + cu * 4;
    const float* bsrc0 = g_W + (size_t)(n0 + crow) * K_TOTAL + cu * 4;
    const uint32_t adst0 = sbase + crow * ROWSTRIDE_B + cu * 16;
    const uint32_t bdst0 = sbase + A_TILE_BYTES + crow * ROWSTRIDE_B + cu * 16;

    // --- ldmatrix per-thread addresses (stage/k offsets added later)
    const int r8 = lane & 7;
    const int g  = lane >> 3;
    uint32_t a_addr[4], b_addr[4];
    #pragma unroll
    for (int mt = 0; mt < 4; ++mt) {
        int arow = wm * 64 + mt * 16 + ((g & 1) << 3) + r8;
        a_addr[mt] = sbase + arow * ROWSTRIDE_B + ((g >> 1) << 4);
    }
    #pragma unroll
    for (int p = 0; p < 4; ++p) {
        int brow = wn * 64 + p * 16 + ((g >> 1) << 3) + r8;
        b_addr[p] = sbase + A_TILE_BYTES + brow * ROWSTRIDE_B + ((g & 1) << 4);
    }

    float c[4][8][4];
    #pragma unroll
    for (int mt = 0; mt < 4; ++mt)
        #pragma unroll
        for (int nt = 0; nt < 8; ++nt)
            #pragma unroll
            for (int i = 0; i < 4; ++i) c[mt][nt][i] = 0.0f;

    // --- prologue: prefetch first NSTAGES-1 k-tiles
    #pragma unroll
    for (int s = 0; s < NSTAGES - 1; ++s) {
        uint32_t soff = s * STAGE_BYTES;
        #pragma unroll
        for (int j = 0; j < 8; ++j) {
            CP_ASYNC16(adst0 + soff + j * (16 * ROWSTRIDE_B),
                       asrc0 + s * BK + (size_t)j * 16 * K_TOTAL);
            CP_ASYNC16(bdst0 + soff + j * (16 * ROWSTRIDE_B),
                       bsrc0 + s * BK + (size_t)j * 16 * K_TOTAL);
        }
        CP_COMMIT();
    }

    // --- main loop
    for (int kt = 0; kt < KTILES; ++kt) {
        CP_WAIT(NSTAGES - 2);
        __syncthreads();

        int nload = kt + NSTAGES - 1;
        if (nload < KTILES) {
            uint32_t soff = (nload % NSTAGES) * STAGE_BYTES;
            #pragma unroll
            for (int j = 0; j < 8; ++j) {
                CP_ASYNC16(adst0 + soff + j * (16 * ROWSTRIDE_B),
                           asrc0 + nload * BK + (size_t)j * 16 * K_TOTAL);
                CP_ASYNC16(bdst0 + soff + j * (16 * ROWSTRIDE_B),
                           bsrc0 + nload * BK + (size_t)j * 16 * K_TOTAL);
            }
        }
        CP_COMMIT();

        const uint32_t soff = (kt % NSTAGES) * STAGE_BYTES;
        #pragma unroll
        for (int kk = 0; kk < 4; ++kk) {          // 4 x k8 steps
            uint32_t a[4][4], b[4][4];
            #pragma unroll
            for (int mt = 0; mt < 4; ++mt)
                LDSM4(a[mt], a_addr[mt] + soff + kk * 32);
            #pragma unroll
            for (int p = 0; p < 4; ++p)
                LDSM4(b[p], b_addr[p] + soff + kk * 32);
            // round A to tf32 (rna) — B was pre-rounded in reduce_w
            #pragma unroll
            for (int mt = 0; mt < 4; ++mt)
                #pragma unroll
                for (int i = 0; i < 4; ++i)
                    a[mt][i] = f2tf32(__uint_as_float(a[mt][i]));
            #pragma unroll
            for (int mt = 0; mt < 4; ++mt)
                #pragma unroll
                for (int nt = 0; nt < 8; ++nt) {
                    const int p = nt >> 1, h = (nt & 1) * 2;
                    MMA_TF32(c[mt][nt], a[mt], b[p][h], b[p][h + 1]);
                }
        }
    }

    // --- epilogue: direct float2 stores of raw y
    #pragma unroll
    for (int mt = 0; mt < 4; ++mt) {
        #pragma unroll
        for (int nt = 0; nt < 8; ++nt) {
            int row = m0 + wm * 64 + mt * 16 + (lane >> 2);
            int col = n0 + wn * 64 + nt * 8 + ((lane & 3) * 2);
            *(float2*)(out + (size_t)row * N_TOTAL + col) =
                make_float2(c[mt][nt][0], c[mt][nt][1]);
            *(float2*)(out + (size_t)(row + 8) * N_TOTAL + col) =
                make_float2(c[mt][nt][2], c[mt][nt][3]);
        }
    }
}

// ---------------------------------------------------------------------------
// Kernel 3: in-place RMSNorm over H=1024 per row
// ---------------------------------------------------------------------------
__global__ void rmsnorm_kernel(float* __restrict__ out, const float* __restrict__ nw) {
    const int row = blockIdx.x;
    const int tid = threadIdx.x;   // 256 threads, 1 float4 each
    float4* p = (float4*)(out + (size_t)row * 1024);
    float4 v = p[tid];
    float ss = v.x * v.x + v.y * v.y + v.z * v.z + v.w * v.w;
    #pragma unroll
    for (int o = 16; o > 0; o >>= 1) ss += __shfl_xor_sync(0xffffffffu, ss, o);
    __shared__ float sred[8];
    if ((tid & 31) == 0) sred[tid >> 5] = ss;
    __syncthreads();
    float tot = sred[0] + sred[1] + sred[2] + sred[3] +
                sred[4] + sred[5] + sred[6] + sred[7];
    float sc = rsqrtf(tot * (1.0f / 1024.0f) + 1e-6f);
    float4 w = ((const float4*)nw)[tid];
    v.x *= sc * w.x; v.y *= sc * w.y; v.z *= sc * w.z; v.w *= sc * w.w;
    p[tid] = v;
}

// ---------------------------------------------------------------------------
extern "C" void kernel_launch(void* const* d_in, const int* in_sizes, int n_in,
                              void* d_out, int out_size) {
    const float* xin = (const float*)d_in[0];
    const float* cw  = (const float*)d_in[1];
    const float* nw  = (const float*)d_in[2];
    float* out = (float*)d_out;

    reduce_w_kernel<<<512, 512>>>(cw);              // 262144 float4

    cudaFuncSetAttribute(gemm_kernel, cudaFuncAttributeMaxDynamicSharedMemorySize,
                         GEMM_SMEM);
    gemm_kernel<<<dim3(N_TOTAL / BN, M_TOTAL / BM), 128, GEMM_SMEM>>>(xin, out);

    rmsnorm_kernel<<<M_TOTAL, 256>>>(out, nw);
}

// round 8
// speedup vs baseline: 1.1498x; 1.0278x over previous
#include <cuda_runtime.h>
#include <cstdint>

#define M_TOTAL 16384
#define N_TOTAL 1024
#define K_TOTAL 1024
#define L_CONV  20

// Scratch: reduced + tf32-rounded weight (device globals are the sanctioned scratch)
__device__ float g_W[(size_t)N_TOTAL * K_TOTAL];   // 4MB

// ---------------------------------------------------------------------------
// Baseline-PTX helpers (sm_80-era features only — no tcgen05 on this target)
// ---------------------------------------------------------------------------
__device__ __forceinline__ uint32_t smem_u32(const void* p) {
    uint32_t a;
    asm("{ .reg .u64 t; cvta.to.shared.u64 t, %1; cvt.u32.u64 %0, t; }"
        : "=r"(a) : "l"(p));
    return a;
}

__device__ __forceinline__ uint32_t f2tf32(float x) {
    uint32_t r;
    asm("cvt.rna.tf32.f32 %0, %1;" : "=r"(r) : "f"(x));
    return r;
}

__device__ __forceinline__ float tf32_rna_f(float x) {
    float r;
    asm("cvt.rna.tf32.f32 %0, %1;" : "=f"(r) : "f"(x));
    return r;
}

#define CP_ASYNC16(dst, src) \
    asm volatile("cp.async.cg.shared.global [%0], [%1], 16;" \
                 :: "r"(dst), "l"(src))
#define CP_COMMIT() asm volatile("cp.async.commit_group;")
#define CP_WAIT(n)  asm volatile("cp.async.wait_group %0;" :: "n"(n))

#define LDSM4(R, addr) \
    asm volatile("ldmatrix.sync.aligned.m8n8.x4.shared.b16 {%0,%1,%2,%3}, [%4];" \
                 : "=r"((R)[0]), "=r"((R)[1]), "=r"((R)[2]), "=r"((R)[3]) \
                 : "r"(addr))

#define MMA_TF32(D, A, B0, B1) \
    asm volatile("mma.sync.aligned.m16n8k8.row.col.f32.tf32.tf32.f32 " \
                 "{%0,%1,%2,%3}, {%4,%5,%6,%7}, {%8,%9}, {%0,%1,%2,%3};" \
                 : "+f"((D)[0]), "+f"((D)[1]), "+f"((D)[2]), "+f"((D)[3]) \
                 : "r"((A)[0]), "r"((A)[1]), "r"((A)[2]), "r"((A)[3]), \
                   "r"(B0), "r"(B1))

// ---------------------------------------------------------------------------
// Kernel 1: W[o,i] = round_tf32( (1/L) * sum_l conv_w[l,o,i] )
//   2048 blocks x 128 threads: ~13.8 blocks/SM -> last-wave imbalance <= 7%
// ---------------------------------------------------------------------------
__global__ __launch_bounds__(128) void reduce_w_kernel(const float* __restrict__ cw) {
    size_t i = (size_t)blockIdx.x * blockDim.x + threadIdx.x;  // over 262144 float4
    const float4* c4 = (const float4*)cw;
    const size_t plane = (size_t)N_TOTAL * K_TOTAL / 4;
    float4 a = c4[i];
    #pragma unroll
    for (int l = 1; l < L_CONV; ++l) {
        float4 v = c4[(size_t)l * plane + i];
        a.x += v.x; a.y += v.y; a.z += v.z; a.w += v.w;
    }
    const float s = 1.0f / (float)L_CONV;
    a.x = tf32_rna_f(a.x * s); a.y = tf32_rna_f(a.y * s);
    a.z = tf32_rna_f(a.z * s); a.w = tf32_rna_f(a.w * s);
    ((float4*)g_W)[i] = a;
}

// ---------------------------------------------------------------------------
// Kernel 2: tf32 GEMM via mma.sync — CTA tile 128x128, BK=32, 3-stage cp.async
//           8 warps (warp tile 32x64), 2 CTAs/SM  [R3 config — proven best]
//   A = x [16384 x 1024] row-major (K-major)
//   B = g_W [1024 x 1024] row-major in (n,k) == col-major B for .row.col mma
// ---------------------------------------------------------------------------
#define BM 128
#define BN 128
#define BK 32
#define ROWSTRIDE_B 144                    // 36 floats: padded, conflict-free
#define TILE_BYTES (128 * ROWSTRIDE_B)     // 18432
#define STAGE_BYTES (2 * TILE_BYTES)       // 36864 (A then B)
#define NSTAGES 3
#define GEMM_SMEM (NSTAGES * STAGE_BYTES)  // 110592
#define KTILES (K_TOTAL / BK)              // 32

__global__ __launch_bounds__(256, 2) void gemm_kernel(const float* __restrict__ x,
                                                      float* __restrict__ out) {
    extern __shared__ __align__(128) char smem[];
    const uint32_t sbase = smem_u32(smem);
    const int tid  = threadIdx.x;
    const int lane = tid & 31;
    const int warp = tid >> 5;
    const int wm = warp & 3;          // 4 warps along M (32 rows each)
    const int wn = warp >> 2;         // 2 warps along N (64 cols each)
    const int m0 = blockIdx.y * BM;
    const int n0 = blockIdx.x * BN;

    // --- global->smem copy assignments: 4 A chunks + 4 B chunks (16B) per thread
    const float* asrc[4];
    const float* bsrc[4];
    uint32_t adst[4], bdst[4];
    #pragma unroll
    for (int j = 0; j < 4; ++j) {
        int id  = tid + j * 256;          // 0..1023
        int row = id >> 3;                // 0..127
        int u   = id & 7;                 // 16B chunk within 128B row
        asrc[j] = x + (size_t)(m0 + row) * K_TOTAL + u * 4;
        bsrc[j] = g_W + (size_t)(n0 + row) * K_TOTAL + u * 4;
        adst[j] = sbase + row * ROWSTRIDE_B + u * 16;
        bdst[j] = sbase + TILE_BYTES + row * ROWSTRIDE_B + u * 16;
    }

    // --- ldmatrix per-thread addresses (stage/k offsets added later)
    const int r8 = lane & 7;
    const int g  = lane >> 3;
    uint32_t a_addr[2], b_addr[4];
    #pragma unroll
    for (int mt = 0; mt < 2; ++mt) {
        int arow = wm * 32 + mt * 16 + ((g & 1) << 3) + r8;
        a_addr[mt] = sbase + arow * ROWSTRIDE_B + ((g >> 1) << 4);
    }
    #pragma unroll
    for (int p = 0; p < 4; ++p) {
        int brow = wn * 64 + p * 16 + ((g >> 1) << 3) + r8;
        b_addr[p] = sbase + TILE_BYTES + brow * ROWSTRIDE_B + ((g & 1) << 4);
    }

    float c[2][8][4];
    #pragma unroll
    for (int mt = 0; mt < 2; ++mt)
        #pragma unroll
        for (int nt = 0; nt < 8; ++nt)
            #pragma unroll
            for (int i = 0; i < 4; ++i) c[mt][nt][i] = 0.0f;

    // --- prologue: prefetch first NSTAGES-1 k-tiles
    #pragma unroll
    for (int s = 0; s < NSTAGES - 1; ++s) {
        uint32_t soff = s * STAGE_BYTES;
        #pragma unroll
        for (int j = 0; j < 4; ++j) {
            CP_ASYNC16(adst[j] + soff, asrc[j] + s * BK);
            CP_ASYNC16(bdst[j] + soff, bsrc[j] + s * BK);
        }
        CP_COMMIT();
    }

    // --- main loop
    for (int kt = 0; kt < KTILES; ++kt) {
        CP_WAIT(NSTAGES - 2);
        __syncthreads();

        int nload = kt + NSTAGES - 1;
        if (nload < KTILES) {
            uint32_t soff = (nload % NSTAGES) * STAGE_BYTES;
            #pragma unroll
            for (int j = 0; j < 4; ++j) {
                CP_ASYNC16(adst[j] + soff, asrc[j] + nload * BK);
                CP_ASYNC16(bdst[j] + soff, bsrc[j] + nload * BK);
            }
        }
        CP_COMMIT();

        const uint32_t soff = (kt % NSTAGES) * STAGE_BYTES;
        #pragma unroll
        for (int kk = 0; kk < 4; ++kk) {          // 4 x k8 steps
            uint32_t a[2][4], b[4][4];
            LDSM4(a[0], a_addr[0] + soff + kk * 32);
            LDSM4(a[1], a_addr[1] + soff + kk * 32);
            #pragma unroll
            for (int p = 0; p < 4; ++p)
                LDSM4(b[p], b_addr[p] + soff + kk * 32);
            // round A to tf32 (rna) — B was pre-rounded in reduce_w
            #pragma unroll
            for (int mt = 0; mt < 2; ++mt)
                #pragma unroll
                for (int i = 0; i < 4; ++i)
                    a[mt][i] = f2tf32(__uint_as_float(a[mt][i]));
            #pragma unroll
            for (int mt = 0; mt < 2; ++mt)
                #pragma unroll
                for (int nt = 0; nt < 8; ++nt) {
                    const int p = nt >> 1, h = (nt & 1) * 2;
                    MMA_TF32(c[mt][nt], a[mt], b[p][h], b[p][h + 1]);
                }
        }
    }

    // --- epilogue: direct float2 stores of raw y
    #pragma unroll
    for (int mt = 0; mt < 2; ++mt) {
        #pragma unroll
        for (int nt = 0; nt < 8; ++nt) {
            int row = m0 + wm * 32 + mt * 16 + (lane >> 2);
            int col = n0 + wn * 64 + nt * 8 + ((lane & 3) * 2);
            *(float2*)(out + (size_t)row * N_TOTAL + col) =
                make_float2(c[mt][nt][0], c[mt][nt][1]);
            *(float2*)(out + (size_t)(row + 8) * N_TOTAL + col) =
                make_float2(c[mt][nt][2], c[mt][nt][3]);
        }
    }
}

// ---------------------------------------------------------------------------
// Kernel 3: in-place RMSNorm over H=1024; 2 rows per 512-thread block
// ---------------------------------------------------------------------------
__global__ __launch_bounds__(512) void rmsnorm_kernel(float* __restrict__ out,
                                                      const float* __restrict__ nw) {
    const int tid  = threadIdx.x;          // 512
    const int rsel = tid >> 8;             // 0 or 1: which row
    const int rt   = tid & 255;            // thread within row
    const int row  = blockIdx.x * 2 + rsel;
    float4* p = (float4*)(out + (size_t)row * 1024);
    float4 v = p[rt];
    float ss = v.x * v.x + v.y * v.y + v.z * v.z + v.w * v.w;
    #pragma unroll
    for (int o = 16; o > 0; o >>= 1) ss += __shfl_xor_sync(0xffffffffu, ss, o);
    __shared__ float sred[16];
    if ((tid & 31) == 0) sred[tid >> 5] = ss;
    __syncthreads();
    const float* sr = sred + rsel * 8;
    float tot = sr[0] + sr[1] + sr[2] + sr[3] + sr[4] + sr[5] + sr[6] + sr[7];
    float sc = rsqrtf(tot * (1.0f / 1024.0f) + 1e-6f);
    float4 w = ((const float4*)nw)[rt];
    v.x *= sc * w.x; v.y *= sc * w.y; v.z *= sc * w.z; v.w *= sc * w.w;
    p[rt] = v;
}

// ---------------------------------------------------------------------------
extern "C" void kernel_launch(void* const* d_in, const int* in_sizes, int n_in,
                              void* d_out, int out_size) {
    const float* xin = (const float*)d_in[0];
    const float* cw  = (const float*)d_in[1];
    const float* nw  = (const float*)d_in[2];
    float* out = (float*)d_out;

    reduce_w_kernel<<<2048, 128>>>(cw);             // 262144 float4, balanced grid

    cudaFuncSetAttribute(gemm_kernel, cudaFuncAttributeMaxDynamicSharedMemorySize,
                         GEMM_SMEM);
    gemm_kernel<<<dim3(N_TOTAL / BN, M_TOTAL / BM), 256, GEMM_SMEM>>>(xin, out);

    rmsnorm_kernel<<<M_TOTAL / 2, 512>>>(out, nw);
}